// round 5
// baseline (speedup 1.0000x reference)
#include <cuda_runtime.h>
#include <cstdint>

// Problem constants
#define MROWS   65536
#define KDIM    48          // s_in = 32 + 16
#define NSPL    32          // spline groups per row
#define NB      33          // 2K+1 outputs per group (17 heights, 16 widths)
#define NPAD    36          // padded group width (ln*36 mod 32 = ln*4 -> LDS.128 conflict-free)
#define NGRP    8           // spline groups per block
#define BM      128         // rows per block
#define THREADS 512         // (BM/2) * NGRP
#define WS_STRIDE (NGRP * NPAD)                 // 288 floats per k-row
#define AST     130                             // transposed A row: 128 rows + 2 pad
#define SMEM_FLOATS (KDIM * WS_STRIDE + KDIM * AST + WS_STRIDE)
#define SMEM_BYTES  (SMEM_FLOATS * 4)           // 81408 B

// ---------- packed f32x2 helpers ----------
__device__ __forceinline__ unsigned long long pack2(float a) {
    unsigned long long r;
    asm("mov.b64 %0, {%1, %1};" : "=l"(r) : "f"(a));
    return r;
}
__device__ __forceinline__ void ffma2(unsigned long long& d,
                                      unsigned long long a,
                                      unsigned long long b) {
    asm("fma.rn.f32x2 %0, %1, %2, %0;" : "+l"(d) : "l"(a), "l"(b));
}

// ---------- quadratic spline (per (m,n) pair) ----------
// y[0..16] = unnormalized heights, y[17..32] = unnormalized widths
__device__ __forceinline__ float spline_eval(const unsigned long long acc[17],
                                             float input, float& x_out) {
    float y[34];
#pragma unroll
    for (int p = 0; p < 17; p++) {
        unsigned int lo = (unsigned int)acc[p];
        unsigned int hi = (unsigned int)(acc[p] >> 32);
        y[2 * p]     = __uint_as_float(lo);
        y[2 * p + 1] = __uint_as_float(hi);
    }

    // h = softplus(uh) + 0.001  (robust softplus, matches jax.nn.softplus)
    float h[17];
#pragma unroll
    for (int i = 0; i < 17; i++) {
        float x = y[i];
        h[i] = fmaxf(x, 0.0f) + log1pf(expf(-fabsf(x))) + 0.001f;
    }

    // widths = MIN_BW + (1 - 16*MIN_BW) * softmax(uw)
    float w[16];
    float esum = 0.0f;
#pragma unroll
    for (int i = 0; i < 16; i++) { w[i] = expf(y[17 + i]); esum += w[i]; }
    float inv = 1.0f / esum;
#pragma unroll
    for (int i = 0; i < 16; i++) w[i] = 0.001f + 0.984f * (w[i] * inv);

    // area & normalized heights
    float area = 0.0f;
#pragma unroll
    for (int i = 0; i < 16; i++) area += (h[i] + h[i + 1]) * 0.5f * w[i];
    float hs = 0.999f / area;   // (1 - MIN_BH)/area
#pragma unroll
    for (int i = 0; i < 17; i++) h[i] = 0.001f + h[i] * hs;

    // sequential scan: locations / left-cdf cumsums + predicated bin select.
    float L = 0.0f, C = 0.0f;
    float bl = 0.0f, bw = w[0], lcdf = 0.0f, hl = h[0], hr = h[1];
#pragma unroll
    for (int i = 1; i <= 15; i++) {
        L += w[i - 1];
        C += 0.5f * (h[i - 1] + h[i]) * w[i - 1];
        if (input >= L) { bl = L; bw = w[i]; lcdf = C; hl = h[i]; hr = h[i + 1]; }
    }

    float aq    = 0.5f * (hr - hl) * bw;
    float bq    = hl * bw;
    float alpha = (input - bl) / bw;
    float o = aq * alpha * alpha + bq * alpha + lcdf;
    x_out = fminf(fmaxf(o, 0.0f), 1.0f);
    return logf(alpha * (hr - hl) + hl);
}

// ---------- prep: copy z2 into x[:, :32], zero log_det ----------
__global__ void prep_kernel(const float* __restrict__ z, float* __restrict__ out) {
    int tid = blockIdx.x * blockDim.x + threadIdx.x;
    const int NC = MROWS * 8;                  // float4 copies for x[:, :32]
    if (tid < NC) {
        int m = tid >> 3, q = tid & 7;
        ((float4*)out)[(size_t)m * 16 + q] = ((const float4*)z)[(size_t)m * 16 + 8 + q];
    } else {
        int u = tid - NC;
        if (u < MROWS / 4) {
            ((float4*)(out + (size_t)MROWS * 64))[u] = make_float4(0.f, 0.f, 0.f, 0.f);
        }
    }
}

// ---------- fused GEMM + spline ----------
__global__ void __launch_bounds__(THREADS, 1)
spline_main_kernel(const float* __restrict__ c, const float* __restrict__ z,
                   const float* __restrict__ W, const float* __restrict__ b,
                   float* __restrict__ out) {
    extern __shared__ float sm[];
    float* Ws = sm;                                   // [48][288]  W slice (group-padded to 36)
    float* As = sm + KDIM * WS_STRIDE;                // [48][130]  A tile, TRANSPOSED [k][row]
    float* bs = As + KDIM * AST;                      // [288]      bias slice (padded to 36)

    const int t       = threadIdx.x;
    const int g       = blockIdx.x;                   // n-group block (0..3)
    const int rowbase = blockIdx.y * BM;

    // W slice: cols [g*264, g*264+264), laid out Ws[k*288 + ln*36 + j]
    for (int idx = t; idx < KDIM * (NGRP * NB); idx += THREADS) {
        int k  = idx / (NGRP * NB);
        int cc = idx - k * (NGRP * NB);
        int ln = cc / NB;
        int j  = cc - ln * NB;
        Ws[k * WS_STRIDE + ln * NPAD + j] = W[(size_t)k * 1056 + g * (NGRP * NB) + cc];
    }
    for (int idx = t; idx < KDIM * NGRP * 3; idx += THREADS) {  // zero pad cols j=33,34,35
        int k  = idx / (NGRP * 3);
        int r  = idx - k * (NGRP * 3);
        int ln = r / 3, j = 33 + (r - ln * 3);
        Ws[k * WS_STRIDE + ln * NPAD + j] = 0.0f;
    }
    if (t < WS_STRIDE) {                                    // bias (padded)
        int ln = t / NPAD, j = t - ln * NPAD;
        bs[t] = (j < NB) ? b[g * (NGRP * NB) + ln * NB + j] : 0.0f;
    }
    // A tile TRANSPOSED: As[k][r]. Cols 0..31 of A = z[:,32:64], cols 32..47 = c.
    // z2 part: BM rows x 8 float4-chunks
    for (int idx = t; idx < BM * 8; idx += THREADS) {
        int q = idx >> 7, r = idx & 127;            // lanes contiguous in r -> STS conflict-free
        float4 v = *(const float4*)&z[(size_t)(rowbase + r) * 64 + 32 + q * 4];
        As[(q * 4 + 0) * AST + r] = v.x;
        As[(q * 4 + 1) * AST + r] = v.y;
        As[(q * 4 + 2) * AST + r] = v.z;
        As[(q * 4 + 3) * AST + r] = v.w;
    }
    // c part: BM rows x 4 float4-chunks
    for (int idx = t; idx < BM * 4; idx += THREADS) {
        int q = idx >> 7, r = idx & 127;
        float4 v = *(const float4*)&c[(size_t)(rowbase + r) * 16 + q * 4];
        As[(32 + q * 4 + 0) * AST + r] = v.x;
        As[(32 + q * 4 + 1) * AST + r] = v.y;
        As[(32 + q * 4 + 2) * AST + r] = v.z;
        As[(32 + q * 4 + 3) * AST + r] = v.w;
    }
    __syncthreads();

    const int ln = t & 7;            // local group in [0,8)
    const int rs = t >> 3;           // row slot in [0,64)
    const int r0 = rs * 2, r1 = r0 + 1;
    const int gn = g * NGRP + ln;    // global spline index in [0,32)

    const float* wcol = Ws + ln * NPAD;
    const unsigned long long* b2 = (const unsigned long long*)(bs + ln * NPAD);

    unsigned long long acc0[17], acc1[17];
#pragma unroll
    for (int p = 0; p < 17; p++) { acc0[p] = b2[p]; acc1[p] = b2[p]; }

#pragma unroll 4
    for (int k = 0; k < KDIM; k++) {
        // both rows in ONE LDS.64 (A transposed, rows contiguous)
        unsigned long long araw = *(const unsigned long long*)(As + k * AST + r0);
        float a0f = __uint_as_float((unsigned int)araw);
        float a1f = __uint_as_float((unsigned int)(araw >> 32));
        unsigned long long ap0 = pack2(a0f);
        unsigned long long ap1 = pack2(a1f);
        const float* wrow = wcol + k * WS_STRIDE;
        // 8 x LDS.128 (conflict-free: banks 4*(ln+p8)+{0..3}) + 1 x LDS.64
#pragma unroll
        for (int p8 = 0; p8 < 8; p8++) {
            ulonglong2 wv = *(const ulonglong2*)(wrow + p8 * 4);
            ffma2(acc0[2 * p8],     ap0, wv.x);
            ffma2(acc1[2 * p8],     ap1, wv.x);
            ffma2(acc0[2 * p8 + 1], ap0, wv.y);
            ffma2(acc1[2 * p8 + 1], ap1, wv.y);
        }
        unsigned long long wt = *(const unsigned long long*)(wrow + 32);
        ffma2(acc0[16], ap0, wt);
        ffma2(acc1[16], ap1, wt);
    }

    // spline + outputs
    const int row0 = rowbase + r0;
    const int row1 = rowbase + r1;
    float x0, x1v;
    float ld0 = spline_eval(acc0, z[(size_t)row0 * 64 + gn], x0);
    float ld1 = spline_eval(acc1, z[(size_t)row1 * 64 + gn], x1v);
    out[(size_t)row0 * 64 + 32 + gn] = x0;
    out[(size_t)row1 * 64 + 32 + gn] = x1v;

    // reduce log_det over the 8 n-lanes of this group (lanes are consecutive)
    ld0 += __shfl_xor_sync(0xffffffffu, ld0, 1);
    ld0 += __shfl_xor_sync(0xffffffffu, ld0, 2);
    ld0 += __shfl_xor_sync(0xffffffffu, ld0, 4);
    ld1 += __shfl_xor_sync(0xffffffffu, ld1, 1);
    ld1 += __shfl_xor_sync(0xffffffffu, ld1, 2);
    ld1 += __shfl_xor_sync(0xffffffffu, ld1, 4);
    if (ln == 0) {
        atomicAdd(&out[(size_t)MROWS * 64 + row0], ld0);
        atomicAdd(&out[(size_t)MROWS * 64 + row1], ld1);
    }
}

extern "C" void kernel_launch(void* const* d_in, const int* in_sizes, int n_in,
                              void* d_out, int out_size) {
    const float* c = (const float*)d_in[0];   // (65536, 16)
    const float* z = (const float*)d_in[1];   // (65536, 64)
    const float* W = (const float*)d_in[2];   // (48, 1056)
    const float* b = (const float*)d_in[3];   // (1056,)
    float* out = (float*)d_out;               // 65536*64 (x) + 65536 (log_det)

    cudaFuncSetAttribute(spline_main_kernel,
                         cudaFuncAttributeMaxDynamicSharedMemorySize, SMEM_BYTES);

    int total = MROWS * 8 + MROWS / 4;
    prep_kernel<<<(total + 255) / 256, 256>>>(z, out);

    dim3 grid(NSPL / NGRP, MROWS / BM);       // (4, 512)
    spline_main_kernel<<<grid, THREADS, SMEM_BYTES>>>(c, z, W, b, out);
}